// round 6
// baseline (speedup 1.0000x reference)
#include <cuda_runtime.h>

#define BDIM 2048
#define TDIM 2048
#define FDIM 12
#define CHUNK 64
#define WARM  96
#define NBLK  296                      /* 2 x 148 SMs: uniform residency */
#define NTHR  256
#define NSCAN 2048                     /* scan warps needed */
#define SCALE (-2.8853900817779268f)   /* -2/ln(2): exp(-2p) = 2^(SCALE*p) */

// Scratch (device globals: allocation-free per harness rules)
__device__ __align__(16) float g_xi[(size_t)TDIM * BDIM * 4];   // [t][b][4], pre-scaled by SCALE
__device__ unsigned int g_bar;                                   // monotonic grid-barrier ticket

__global__ void __launch_bounds__(NTHR, 2) fused_kernel(
    const float* __restrict__ x, const float* __restrict__ embed,
    const float* __restrict__ W1, const float* __restrict__ b1,
    const float* __restrict__ W2, const float* __restrict__ b2,
    const float* __restrict__ Wi, const float* __restrict__ bi,
    const float* __restrict__ Wh, const float* __restrict__ W3,
    const float* __restrict__ b3, const float* __restrict__ W4,
    const float* __restrict__ b4, float* __restrict__ out)
{
    __shared__ float smem_buf[8 * 32 * 33];   // phase A: sxi transpose tile; phase B: per-warp sy tiles
    __shared__ float s_w1[64], s_b1[4];

    int s = threadIdx.x;
    if (s < 64) s_w1[s] = W1[s];
    if (s < 4)  s_b1[s] = b1[s];

    // Per-thread fused weights: W2i = (W2@Wi)*SCALE, b2i = (b2@Wi + bi)*SCALE
    float w2i[16], b2i[4];
    {
        float wiv[16], w2v[16];
        #pragma unroll
        for (int q = 0; q < 16; q++) { wiv[q] = __ldg(Wi + q); w2v[q] = __ldg(W2 + q); }
        #pragma unroll
        for (int k = 0; k < 4; k++) {
            #pragma unroll
            for (int d = 0; d < 4; d++) {
                float acc = 0.f;
                #pragma unroll
                for (int m = 0; m < 4; m++) acc = fmaf(w2v[k * 4 + m], wiv[m * 4 + d], acc);
                w2i[k * 4 + d] = acc * SCALE;
            }
        }
        #pragma unroll
        for (int d = 0; d < 4; d++) {
            float acc = __ldg(bi + d);
            #pragma unroll
            for (int m = 0; m < 4; m++) acc = fmaf(__ldg(b2 + m), wiv[m * 4 + d], acc);
            b2i[d] = acc * SCALE;
        }
    }
    float w1x[48];
    #pragma unroll
    for (int q = 0; q < 48; q++) w1x[q] = __ldg(W1 + q);
    __syncthreads();

    // ---------------- Phase A: g_xi[t][b] = SCALE*(relu(x@W1x + cb)@W2i + b2i)
    {
        float4* sxi = (float4*)smem_buf;            // [32][33]
        int bl = s >> 3, tl0 = s & 7;
        for (int tIdx = blockIdx.x; tIdx < 64 * 64; tIdx += NBLK) {
            int b0 = (tIdx & 63) * 32;
            int t0 = (tIdx >> 6) * 32;
            int b  = b0 + bl;
            float4 e4 = ((const float4*)embed)[b];
            float cb[4];
            #pragma unroll
            for (int d = 0; d < 4; d++) {
                float cc = s_b1[d];
                cc = fmaf(e4.x, s_w1[48 + d], cc);
                cc = fmaf(e4.y, s_w1[52 + d], cc);
                cc = fmaf(e4.z, s_w1[56 + d], cc);
                cc = fmaf(e4.w, s_w1[60 + d], cc);
                cb[d] = cc;
            }
            #pragma unroll
            for (int i = 0; i < 4; i++) {
                int tl = tl0 + 8 * i;
                const float4* xp4 = (const float4*)(x + ((size_t)b * TDIM + (size_t)(t0 + tl)) * FDIM);
                float4 xa = xp4[0], xb = xp4[1], xc = xp4[2];
                float xv[12] = {xa.x, xa.y, xa.z, xa.w, xb.x, xb.y, xb.z, xb.w, xc.x, xc.y, xc.z, xc.w};
                float u[4] = {cb[0], cb[1], cb[2], cb[3]};
                #pragma unroll
                for (int f = 0; f < 12; f++) {
                    #pragma unroll
                    for (int d = 0; d < 4; d++) u[d] = fmaf(xv[f], w1x[f * 4 + d], u[d]);
                }
                #pragma unroll
                for (int d = 0; d < 4; d++) u[d] = fmaxf(u[d], 0.f);
                float o[4] = {b2i[0], b2i[1], b2i[2], b2i[3]};
                #pragma unroll
                for (int k = 0; k < 4; k++) {
                    #pragma unroll
                    for (int d = 0; d < 4; d++) o[d] = fmaf(u[k], w2i[k * 4 + d], o[d]);
                }
                sxi[tl * 33 + bl] = make_float4(o[0], o[1], o[2], o[3]);
            }
            __syncthreads();
            int bl2 = s & 31, th = s >> 5;
            #pragma unroll
            for (int i = 0; i < 4; i++) {
                int tt = th + 8 * i;
                ((float4*)g_xi)[(size_t)(t0 + tt) * BDIM + (b0 + bl2)] = sxi[tt * 33 + bl2];
            }
            __syncthreads();
        }
    }

    // ---------------- Grid barrier (ticket-based; robust across graph replays)
    if (s == 0) {
        __threadfence();
        unsigned t = atomicAdd(&g_bar, 1u);
        unsigned target = (t / NBLK + 1u) * NBLK;
        while (*(volatile unsigned*)&g_bar < target) __nanosleep(64);
        __threadfence();
    }
    __syncthreads();

    // ---------------- Phase B: chunked scan (warmup WARM) + fused output head
    {
        int wl = s >> 5, lane = s & 31;
        int sid = wl * NBLK + blockIdx.x;         // 0..2367; wl=0..6 nearly all active
        if (sid < NSCAN) {
            float whs[16];
            #pragma unroll
            for (int q = 0; q < 16; q++) whs[q] = __ldg(Wh + q) * SCALE;
            float w3[24];
            #pragma unroll
            for (int q = 0; q < 24; q++) w3[q] = __ldg(W3 + q);
            float b3v[6], w4v[6];
            #pragma unroll
            for (int q = 0; q < 6; q++) { b3v[q] = __ldg(b3 + q); w4v[q] = __ldg(W4 + q); }
            float b4v = __ldg(b4);

            int bw = sid & 63, c = sid >> 6;      // 64 row-groups x 32 chunks
            int b  = bw * 32 + lane, b0 = bw * 32;

            int base, nTiles, warmTiles;
            if (c == 0)      { base = 0;                 nTiles = 2; warmTiles = 0; }
            else if (c == 1) { base = 0;                 nTiles = 4; warmTiles = 2; }
            else             { base = c * CHUNK - WARM;  nTiles = 5; warmTiles = 3; }

            float* sy = smem_buf + wl * 32 * 33;  // per-warp [t][b] tile, pad 33
            const float4* xp = (const float4*)g_xi;
            float h0 = 0.f, h1 = 0.f, h2 = 0.f, h3 = 0.f;

            const int U = 8;
            float4 bufA[U], bufB[U];
            #pragma unroll
            for (int u = 0; u < U; u++) bufA[u] = xp[(size_t)(base + u) * BDIM + b];

            int tb = 0;
            for (int tile = 0; tile < nTiles; ++tile) {
                bool doStore = (tile >= warmTiles);
                #pragma unroll
                for (int half = 0; half < 2; ++half) {
                    #pragma unroll
                    for (int u = 0; u < U; u++) {
                        int tt = base + tb + U + u; if (tt >= TDIM) tt = TDIM - 1;
                        bufB[u] = xp[(size_t)tt * BDIM + b];
                    }
                    #pragma unroll
                    for (int u = 0; u < U; u++) {
                        float4 v = bufA[u];
                        float q0 = v.x + h0 * whs[0] + h1 * whs[4] + h2 * whs[8]  + h3 * whs[12];
                        float q1 = v.y + h0 * whs[1] + h1 * whs[5] + h2 * whs[9]  + h3 * whs[13];
                        float q2 = v.z + h0 * whs[2] + h1 * whs[6] + h2 * whs[10] + h3 * whs[14];
                        float q3 = v.w + h0 * whs[3] + h1 * whs[7] + h2 * whs[11] + h3 * whs[15];
                        float e0, e1, e2, e3, r0, r1, r2, r3;
                        asm("ex2.approx.f32 %0, %1;" : "=f"(e0) : "f"(q0));
                        asm("ex2.approx.f32 %0, %1;" : "=f"(e1) : "f"(q1));
                        asm("ex2.approx.f32 %0, %1;" : "=f"(e2) : "f"(q2));
                        asm("ex2.approx.f32 %0, %1;" : "=f"(e3) : "f"(q3));
                        asm("rcp.approx.f32 %0, %1;" : "=f"(r0) : "f"(e0 + 1.0f));
                        asm("rcp.approx.f32 %0, %1;" : "=f"(r1) : "f"(e1 + 1.0f));
                        asm("rcp.approx.f32 %0, %1;" : "=f"(r2) : "f"(e2 + 1.0f));
                        asm("rcp.approx.f32 %0, %1;" : "=f"(r3) : "f"(e3 + 1.0f));
                        h0 = (1.0f - e0) * r0; h1 = (1.0f - e1) * r1;
                        h2 = (1.0f - e2) * r2; h3 = (1.0f - e3) * r3;
                        if (doStore) {
                            float y = b4v;
                            #pragma unroll
                            for (int j = 0; j < 6; j++) {
                                float z = b3v[j];
                                z = fmaf(h0, w3[j],      z);
                                z = fmaf(h1, w3[6 + j],  z);
                                z = fmaf(h2, w3[12 + j], z);
                                z = fmaf(h3, w3[18 + j], z);
                                z = fmaxf(z, 0.f);
                                y = fmaf(z, w4v[j], y);
                            }
                            sy[((tb + u) & 31) * 33 + lane] = y;
                        }
                    }
                    #pragma unroll
                    for (int u = 0; u < U; u++) {
                        int tt = base + tb + 2 * U + u; if (tt >= TDIM) tt = TDIM - 1;
                        bufA[u] = xp[(size_t)tt * BDIM + b];
                    }
                    #pragma unroll
                    for (int u = 0; u < U; u++) {
                        float4 v = bufB[u];
                        float q0 = v.x + h0 * whs[0] + h1 * whs[4] + h2 * whs[8]  + h3 * whs[12];
                        float q1 = v.y + h0 * whs[1] + h1 * whs[5] + h2 * whs[9]  + h3 * whs[13];
                        float q2 = v.z + h0 * whs[2] + h1 * whs[6] + h2 * whs[10] + h3 * whs[14];
                        float q3 = v.w + h0 * whs[3] + h1 * whs[7] + h2 * whs[11] + h3 * whs[15];
                        float e0, e1, e2, e3, r0, r1, r2, r3;
                        asm("ex2.approx.f32 %0, %1;" : "=f"(e0) : "f"(q0));
                        asm("ex2.approx.f32 %0, %1;" : "=f"(e1) : "f"(q1));
                        asm("ex2.approx.f32 %0, %1;" : "=f"(e2) : "f"(q2));
                        asm("ex2.approx.f32 %0, %1;" : "=f"(e3) : "f"(q3));
                        asm("rcp.approx.f32 %0, %1;" : "=f"(r0) : "f"(e0 + 1.0f));
                        asm("rcp.approx.f32 %0, %1;" : "=f"(r1) : "f"(e1 + 1.0f));
                        asm("rcp.approx.f32 %0, %1;" : "=f"(r2) : "f"(e2 + 1.0f));
                        asm("rcp.approx.f32 %0, %1;" : "=f"(r3) : "f"(e3 + 1.0f));
                        h0 = (1.0f - e0) * r0; h1 = (1.0f - e1) * r1;
                        h2 = (1.0f - e2) * r2; h3 = (1.0f - e3) * r3;
                        if (doStore) {
                            float y = b4v;
                            #pragma unroll
                            for (int j = 0; j < 6; j++) {
                                float z = b3v[j];
                                z = fmaf(h0, w3[j],      z);
                                z = fmaf(h1, w3[6 + j],  z);
                                z = fmaf(h2, w3[12 + j], z);
                                z = fmaf(h3, w3[18 + j], z);
                                z = fmaxf(z, 0.f);
                                y = fmaf(z, w4v[j], y);
                            }
                            sy[((tb + U + u) & 31) * 33 + lane] = y;
                        }
                    }
                    tb += 16;
                }
                if (doStore) {
                    __syncwarp();
                    int tileT = base + tile * 32;
                    #pragma unroll 8
                    for (int j = 0; j < 32; j++) {
                        out[(size_t)(b0 + j) * TDIM + tileT + lane] = sy[lane * 33 + j];
                    }
                    __syncwarp();
                }
            }
        }
    }
}

// ---------------------------------------------------------------- launch
extern "C" void kernel_launch(void* const* d_in, const int* in_sizes, int n_in,
                              void* d_out, int out_size) {
    const float* x     = (const float*)d_in[0];
    const float* embed = (const float*)d_in[1];
    const float* W1    = (const float*)d_in[2];
    const float* b1    = (const float*)d_in[3];
    const float* W2    = (const float*)d_in[4];
    const float* b2    = (const float*)d_in[5];
    const float* Wi    = (const float*)d_in[6];
    const float* bi    = (const float*)d_in[7];
    const float* Wh    = (const float*)d_in[8];
    const float* W3    = (const float*)d_in[9];
    const float* b3    = (const float*)d_in[10];
    const float* W4    = (const float*)d_in[11];
    const float* b4    = (const float*)d_in[12];
    float* out = (float*)d_out;

    fused_kernel<<<NBLK, NTHR>>>(x, embed, W1, b1, W2, b2, Wi, bi, Wh, W3, b3, W4, b4, out);
}